// round 1
// baseline (speedup 1.0000x reference)
#include <cuda_runtime.h>
#include <math.h>

#define B_   32
#define D_   128
#define LC_  2048
#define LQ_  512

typedef unsigned long long ull;

// ---------------- scratch (device globals: no alloc allowed) ----------------
__device__ float g_E[(size_t)B_ * LC_ * LQ_];   // E = qmask * exp(S)   (134 MB)
__device__ float g_s0[B_ * LC_];
__device__ float g_s1[B_ * LQ_];
__device__ float g_rZ1[B_ * LC_];
__device__ float g_rZ2[B_ * LQ_];
__device__ float g_T[B_ * LQ_ * D_];            // T = S2^T @ Ct  (8 MB)

// ---------------- packed f32x2 helpers ----------------
__device__ __forceinline__ ull pk2(float x) {
    ull r; asm("mov.b64 %0, {%1, %1};" : "=l"(r) : "f"(x)); return r;
}
__device__ __forceinline__ void fma2(ull &d, ull a, ull b) {
    asm("fma.rn.f32x2 %0, %1, %2, %0;" : "+l"(d) : "l"(a), "l"(b));
}
__device__ __forceinline__ float2 up2(ull v) {
    float2 r; asm("mov.b64 {%0, %1}, %2;" : "=f"(r.x), "=f"(r.y) : "l"(v)); return r;
}

// =====================================================================
// k_vec: s0[b,c] = Ct . w_c + bias ; s1[b,q] = Qt . w_q
// =====================================================================
__global__ void k_vec(const float* __restrict__ C, const float* __restrict__ Q,
                      const float* __restrict__ w_c, const float* __restrict__ w_q,
                      const float* __restrict__ bias) {
    __shared__ float w[128];
    int t = threadIdx.x;
    bool isQ = blockIdx.x >= 256;
    const float* W = isQ ? w_q : w_c;
    if (t < 128) w[t] = W[t];
    __syncthreads();
    if (!isQ) {
        int idx = blockIdx.x * 256 + t;           // b*LC + c
        int b = idx >> 11, c = idx & (LC_ - 1);
        const float* base = C + (size_t)b * D_ * LC_ + c;
        float acc = bias[0];
        #pragma unroll 8
        for (int dd = 0; dd < 128; dd++) acc += base[dd * LC_] * w[dd];
        g_s0[idx] = acc;
    } else {
        int idx = (blockIdx.x - 256) * 256 + t;   // b*LQ + q
        int b = idx >> 9, q = idx & (LQ_ - 1);
        const float* base = Q + (size_t)b * D_ * LQ_ + q;
        float acc = 0.f;
        #pragma unroll 8
        for (int dd = 0; dd < 128; dd++) acc += base[dd * LQ_] * w[dd];
        g_s1[idx] = acc;
    }
}

// =====================================================================
// k_S: E[b,c,q] = qmask[q] * exp( (Ct*w_mul) @ Qt^T + s0[c] + s1[q] )
// GEMM M=Lc N=Lq K=128, tile 128x128, K-chunk 32
// =====================================================================
__global__ void __launch_bounds__(256) k_S(const float* __restrict__ C,
                                           const float* __restrict__ Q,
                                           const float* __restrict__ w_mul,
                                           const int* __restrict__ Qmask) {
    __shared__ float As[32 * 132];   // [kk][m]  (Ct * w_mul)
    __shared__ float Bs[32 * 132];   // [kk][n]  (Qt)
    __shared__ float wm[128];
    int b = blockIdx.z;
    int cBase = blockIdx.y * 128, qBase = blockIdx.x * 128;
    int tid = threadIdx.x, tx = tid & 15, ty = tid >> 4;
    if (tid < 128) wm[tid] = w_mul[tid];
    __syncthreads();
    const float* Cb = C + (size_t)b * D_ * LC_;
    const float* Qb = Q + (size_t)b * D_ * LQ_;
    ull acc[8][4] = {};
    for (int k0 = 0; k0 < 128; k0 += 32) {
        #pragma unroll
        for (int p = 0; p < 16; p++) {
            int idx = tid + p * 256;
            int kk = idx >> 7, m = idx & 127;
            As[kk * 132 + m] = Cb[(k0 + kk) * LC_ + cBase + m] * wm[k0 + kk];
            Bs[kk * 132 + m] = Qb[(k0 + kk) * LQ_ + qBase + m];
        }
        __syncthreads();
        #pragma unroll
        for (int kk = 0; kk < 32; kk++) {
            float4 a0 = *(const float4*)&As[kk * 132 + ty * 4];
            float4 a1 = *(const float4*)&As[kk * 132 + 64 + ty * 4];
            ulonglong2 b0 = *(const ulonglong2*)&Bs[kk * 132 + tx * 4];
            ulonglong2 b1 = *(const ulonglong2*)&Bs[kk * 132 + 64 + tx * 4];
            ull av[8] = {pk2(a0.x), pk2(a0.y), pk2(a0.z), pk2(a0.w),
                         pk2(a1.x), pk2(a1.y), pk2(a1.z), pk2(a1.w)};
            ull bv[4] = {b0.x, b0.y, b1.x, b1.y};
            #pragma unroll
            for (int i = 0; i < 8; i++)
                #pragma unroll
                for (int j = 0; j < 4; j++) fma2(acc[i][j], av[i], bv[j]);
        }
        __syncthreads();
    }
    // epilogue: + s0 + s1, exp, qmask, store E
    float s0v[8];
    int rows[8];
    #pragma unroll
    for (int i = 0; i < 8; i++) {
        int r = (i < 4) ? ty * 4 + i : 64 + ty * 4 + (i - 4);
        rows[i] = cBase + r;
        s0v[i] = g_s0[b * LC_ + rows[i]];
    }
    float s1v[8]; int qmv[8];
    #pragma unroll
    for (int j = 0; j < 8; j++) {
        int qc = qBase + ((j < 4) ? tx * 4 + j : 64 + tx * 4 + (j - 4));
        s1v[j] = g_s1[b * LQ_ + qc];
        qmv[j] = Qmask[b * LQ_ + qc];
    }
    float* Eb = g_E + (size_t)b * LC_ * LQ_;
    #pragma unroll
    for (int i = 0; i < 8; i++) {
        float v[8];
        #pragma unroll
        for (int j = 0; j < 4; j++) {
            float2 p = up2(acc[i][j]);
            v[2 * j] = p.x; v[2 * j + 1] = p.y;
        }
        float w[8];
        #pragma unroll
        for (int j = 0; j < 8; j++)
            w[j] = qmv[j] ? __expf(v[j] + s0v[i] + s1v[j]) : 0.f;
        float* rowp = Eb + rows[i] * LQ_ + qBase;
        *(float4*)(rowp + tx * 4)      = make_float4(w[0], w[1], w[2], w[3]);
        *(float4*)(rowp + 64 + tx * 4) = make_float4(w[4], w[5], w[6], w[7]);
    }
}

// =====================================================================
// k_Z1: rZ1[b,c] = 1 / rowsum(E)   (one warp per row)
// =====================================================================
__global__ void k_Z1() {
    int row = blockIdx.x * 8 + (threadIdx.x >> 5);
    int lane = threadIdx.x & 31;
    const float* Er = g_E + (size_t)row * LQ_;
    float s = 0.f;
    #pragma unroll
    for (int i = 0; i < 16; i++) s += Er[lane + i * 32];
    #pragma unroll
    for (int o = 16; o; o >>= 1) s += __shfl_xor_sync(0xffffffffu, s, o);
    if (lane == 0) g_rZ1[row] = 1.f / s;
}

// =====================================================================
// k_Z2: rZ2[b,q] = 1 / max(sum_c cmask[c]*E[c,q], tiny)
// =====================================================================
__global__ void k_Z2(const int* __restrict__ Cmask) {
    int b = blockIdx.y;
    int q = blockIdx.x * 128 + (threadIdx.x & 127);
    int half = threadIdx.x >> 7;
    const float* Eb = g_E + (size_t)b * LC_ * LQ_;
    const int* cm = Cmask + b * LC_;
    float s = 0.f;
    int c0 = half * 1024;
    #pragma unroll 4
    for (int c = c0; c < c0 + 1024; c++) {
        if (cm[c]) s += Eb[(size_t)c * LQ_ + q];
    }
    __shared__ float red[256];
    red[threadIdx.x] = s;
    __syncthreads();
    if (threadIdx.x < 128) {
        float tot = red[threadIdx.x] + red[threadIdx.x + 128];
        g_rZ2[b * LQ_ + q] = 1.f / fmaxf(tot, 1e-30f);
    }
}

// =====================================================================
// k_T: T[b,q,dd] = rZ2[q] * sum_c (cm[c]*E[c,q]) * C[b,dd,c]
// GEMM M=Lq(tile 64) N=128 K=Lc(chunk 32)
// =====================================================================
__global__ void __launch_bounds__(256) k_T(const float* __restrict__ C,
                                           const int* __restrict__ Cmask) {
    __shared__ float As[32 * 68];    // [cc][qq<64]  masked E
    __shared__ float Bs[32 * 132];   // [cc][dd]     C (transposed store)
    int b = blockIdx.y;
    int qBase = blockIdx.x * 64;
    int tid = threadIdx.x, tx = tid & 15, ty = tid >> 4;
    const float* Eb = g_E + (size_t)b * LC_ * LQ_;
    const float* Cb = C + (size_t)b * D_ * LC_;
    const int* cm = Cmask + b * LC_;
    ull acc[4][4] = {};
    for (int c0 = 0; c0 < LC_; c0 += 32) {
        #pragma unroll
        for (int p = 0; p < 8; p++) {
            int idx = tid + p * 256;              // 2048 elems
            int cc = idx >> 6, qq = idx & 63;
            As[cc * 68 + qq] = cm[c0 + cc] ? Eb[(size_t)(c0 + cc) * LQ_ + qBase + qq] : 0.f;
        }
        #pragma unroll
        for (int p = 0; p < 16; p++) {
            int idx = tid + p * 256;              // 4096 elems
            int dd = idx >> 5, cc = idx & 31;
            Bs[cc * 132 + dd] = Cb[dd * LC_ + c0 + cc];
        }
        __syncthreads();
        #pragma unroll
        for (int kk = 0; kk < 32; kk++) {
            float4 a0 = *(const float4*)&As[kk * 68 + ty * 4];
            ulonglong2 b0 = *(const ulonglong2*)&Bs[kk * 132 + tx * 4];
            ulonglong2 b1 = *(const ulonglong2*)&Bs[kk * 132 + 64 + tx * 4];
            ull av[4] = {pk2(a0.x), pk2(a0.y), pk2(a0.z), pk2(a0.w)};
            ull bv[4] = {b0.x, b0.y, b1.x, b1.y};
            #pragma unroll
            for (int i = 0; i < 4; i++)
                #pragma unroll
                for (int j = 0; j < 4; j++) fma2(acc[i][j], av[i], bv[j]);
        }
        __syncthreads();
    }
    #pragma unroll
    for (int i = 0; i < 4; i++) {
        int q = qBase + ty * 4 + i;
        float rz = g_rZ2[b * LQ_ + q];
        float* Tr = g_T + (size_t)(b * LQ_ + q) * D_;
        #pragma unroll
        for (int j = 0; j < 4; j++) {
            float2 v = up2(acc[i][j]);
            int col = (j < 2) ? tx * 4 + 2 * j : 64 + tx * 4 + 2 * (j - 2);
            Tr[col]     = v.x * rz;
            Tr[col + 1] = v.y * rz;
        }
    }
}

// =====================================================================
// k_AB: fused  A = S1 @ Qt,  Bm = S1 @ T,  + full output assembly.
// GEMM M=128(c) K=Lq N=128+128, tile 128, K-chunk 32.
// =====================================================================
__global__ void __launch_bounds__(256, 1) k_AB(const float* __restrict__ C,
                                               const float* __restrict__ Q,
                                               float* __restrict__ out) {
    extern __shared__ float dyn[];
    float* As = dyn;                 // [32][132] E tile, [qq][cc] (transposed)
    float* Bq = dyn + 32 * 132;      // [32][132] Qt tile [qq][dd] (transposed)
    float* Bt = dyn + 2 * 32 * 132;  // [32][132] T  tile [qq][dd] (natural)
    int b = blockIdx.y;
    int cBase = blockIdx.x * 128;
    int tid = threadIdx.x, tx = tid & 15, ty = tid >> 4;
    const float* Eb = g_E + (size_t)b * LC_ * LQ_;
    const float* Qb = Q + (size_t)b * D_ * LQ_;
    const float* Tb = g_T + (size_t)b * LQ_ * D_;

    ull accA[8][4] = {}, accB[8][4] = {};
    for (int q0 = 0; q0 < LQ_; q0 += 32) {
        #pragma unroll
        for (int p = 0; p < 16; p++) {
            int idx = tid + p * 256;
            int ci = idx >> 5, qq = idx & 31;
            As[qq * 132 + ci] = Eb[(size_t)(cBase + ci) * LQ_ + q0 + qq];
        }
        #pragma unroll
        for (int p = 0; p < 16; p++) {
            int idx = tid + p * 256;
            int dd = idx >> 5, qq = idx & 31;
            Bq[qq * 132 + dd] = Qb[dd * LQ_ + q0 + qq];
        }
        #pragma unroll
        for (int p = 0; p < 16; p++) {
            int idx = tid + p * 256;
            int qq = idx >> 7, dd = idx & 127;
            Bt[qq * 132 + dd] = Tb[(q0 + qq) * D_ + dd];
        }
        __syncthreads();
        #pragma unroll 8
        for (int kk = 0; kk < 32; kk++) {
            float4 a0 = *(const float4*)&As[kk * 132 + ty * 4];
            float4 a1 = *(const float4*)&As[kk * 132 + 64 + ty * 4];
            ull av[8] = {pk2(a0.x), pk2(a0.y), pk2(a0.z), pk2(a0.w),
                         pk2(a1.x), pk2(a1.y), pk2(a1.z), pk2(a1.w)};
            ulonglong2 q0v = *(const ulonglong2*)&Bq[kk * 132 + tx * 4];
            ulonglong2 q1v = *(const ulonglong2*)&Bq[kk * 132 + 64 + tx * 4];
            ulonglong2 t0v = *(const ulonglong2*)&Bt[kk * 132 + tx * 4];
            ulonglong2 t1v = *(const ulonglong2*)&Bt[kk * 132 + 64 + tx * 4];
            ull bqv[4] = {q0v.x, q0v.y, q1v.x, q1v.y};
            ull btv[4] = {t0v.x, t0v.y, t1v.x, t1v.y};
            #pragma unroll
            for (int i = 0; i < 8; i++) {
                #pragma unroll
                for (int j = 0; j < 4; j++) {
                    fma2(accA[i][j], av[i], bqv[j]);
                    fma2(accB[i][j], av[i], btv[j]);
                }
            }
        }
        __syncthreads();
    }

    float rz[8]; int rloc[8];
    #pragma unroll
    for (int i = 0; i < 8; i++) {
        rloc[i] = (i < 4) ? ty * 4 + i : 64 + ty * 4 + (i - 4);
        rz[i] = g_rZ1[b * LC_ + cBase + rloc[i]];
    }
    float* stage = dyn;  // [128][129], overlaps GEMM buffers (post-sync)
    float* outb = out + (size_t)b * (4 * D_) * LC_;
    const float* Cb = C + (size_t)b * D_ * LC_;

    // ---- pass A: write sections 0 (C), 1 (A), 2 (C*A)
    #pragma unroll
    for (int i = 0; i < 8; i++)
        #pragma unroll
        for (int j = 0; j < 4; j++) {
            float2 v = up2(accA[i][j]);
            int col = (j < 2) ? tx * 4 + 2 * j : 64 + tx * 4 + 2 * (j - 2);
            stage[rloc[i] * 129 + col]     = v.x * rz[i];
            stage[rloc[i] * 129 + col + 1] = v.y * rz[i];
        }
    __syncthreads();
    for (int idx = tid; idx < 128 * 128; idx += 256) {
        int dd = idx >> 7, c = idx & 127;
        float a = stage[c * 129 + dd];
        float cv = Cb[dd * LC_ + cBase + c];
        outb[(size_t)dd * LC_ + cBase + c]            = cv;
        outb[(size_t)(128 + dd) * LC_ + cBase + c]    = a;
        outb[(size_t)(256 + dd) * LC_ + cBase + c]    = cv * a;
    }
    __syncthreads();
    // ---- pass B: write section 3 (C*Bm)
    #pragma unroll
    for (int i = 0; i < 8; i++)
        #pragma unroll
        for (int j = 0; j < 4; j++) {
            float2 v = up2(accB[i][j]);
            int col = (j < 2) ? tx * 4 + 2 * j : 64 + tx * 4 + 2 * (j - 2);
            stage[rloc[i] * 129 + col]     = v.x * rz[i];
            stage[rloc[i] * 129 + col + 1] = v.y * rz[i];
        }
    __syncthreads();
    for (int idx = tid; idx < 128 * 128; idx += 256) {
        int dd = idx >> 7, c = idx & 127;
        float bm = stage[c * 129 + dd];
        float cv = Cb[dd * LC_ + cBase + c];
        outb[(size_t)(384 + dd) * LC_ + cBase + c] = cv * bm;
    }
}

// =====================================================================
extern "C" void kernel_launch(void* const* d_in, const int* in_sizes, int n_in,
                              void* d_out, int out_size) {
    const float* C     = (const float*)d_in[0];
    const float* Q     = (const float*)d_in[1];
    const int*   Cmask = (const int*)  d_in[2];
    const int*   Qmask = (const int*)  d_in[3];
    const float* w_c   = (const float*)d_in[4];
    const float* w_q   = (const float*)d_in[5];
    const float* w_mul = (const float*)d_in[6];
    const float* bias  = (const float*)d_in[7];
    float* out = (float*)d_out;

    k_vec<<<320, 256>>>(C, Q, w_c, w_q, bias);
    k_S<<<dim3(4, 16, 32), 256>>>(C, Q, w_mul, Qmask);
    k_Z1<<<(B_ * LC_) / 8, 256>>>();
    k_Z2<<<dim3(4, 32), 256>>>(Cmask);
    k_T<<<dim3(8, 32), 256>>>(C, Cmask);

    const int dynBytes = 128 * 129 * 4;  // 66048 B (stage dominates)
    cudaFuncSetAttribute(k_AB, cudaFuncAttributeMaxDynamicSharedMemorySize, dynBytes);
    k_AB<<<dim3(16, 32), 256, dynBytes>>>(C, Q, out);
}